// round 5
// baseline (speedup 1.0000x reference)
#include <cuda_runtime.h>
#include <cuda_bf16.h>
#include <cstdint>

// ---------------------------------------------------------------------------
#define NB   32
#define C    1024
#define S    1024
#define BM   128
#define BN   128
#define BK   64                       // 64 bf16 = 128 B per tile row
#define NCHUNK (S / BK)               // 16
#define TILES_PER_BATCH 36
#define NBLK2 (NB * TILES_PER_BATCH)  // 1152
#define TPB  256
#define STAGES 3
#define TILE_BYTES (BM * 128)         // 16384
#define STAGE_BYTES (2 * TILE_BYTES)
#define DSMEM_BYTES (STAGES * STAGE_BYTES)   // 98304

__device__ __nv_bfloat16 g_xn[(size_t)NB * C * S];
__device__ float g_partials[NBLK2];

// ---------------------------------------------------------------------------
__device__ __forceinline__ void cp_async16(uint32_t smem_addr, const void* gptr) {
    asm volatile("cp.async.cg.shared.global [%0], [%1], 16;" :: "r"(smem_addr), "l"(gptr));
}
#define CP_COMMIT() asm volatile("cp.async.commit_group;" ::: "memory")
#define CP_WAIT(n)  asm volatile("cp.async.wait_group %0;" :: "n"(n) : "memory")

__device__ __forceinline__ void ldm_x4(uint32_t& r0, uint32_t& r1, uint32_t& r2, uint32_t& r3,
                                       uint32_t addr) {
    asm volatile("ldmatrix.sync.aligned.m8n8.x4.shared.b16 {%0,%1,%2,%3}, [%4];\n"
                 : "=r"(r0), "=r"(r1), "=r"(r2), "=r"(r3) : "r"(addr));
}

__device__ __forceinline__ void mma16816(float* d, const uint32_t* a, const uint32_t* b) {
    asm volatile("mma.sync.aligned.m16n8k16.row.col.f32.bf16.bf16.f32 "
                 "{%0,%1,%2,%3}, {%4,%5,%6,%7}, {%8,%9}, {%0,%1,%2,%3};\n"
                 : "+f"(d[0]), "+f"(d[1]), "+f"(d[2]), "+f"(d[3])
                 : "r"(a[0]), "r"(a[1]), "r"(a[2]), "r"(a[3]), "r"(b[0]), "r"(b[1]));
}

// XOR swizzle for 128B rows (SW128-equivalent)
__device__ __forceinline__ uint32_t swz(int row, int col_elems) {
    uint32_t chunk = (uint32_t)(col_elems >> 3);
    return (uint32_t)(row * 128) + (((chunk ^ ((uint32_t)row & 7u)) << 4));
}

// ---------------------------------------------------------------------------
// Kernel 1: normalize — one warp per row
// ---------------------------------------------------------------------------
__global__ __launch_bounds__(256) void normalize_kernel(const float* __restrict__ x) {
    const int wid  = threadIdx.x >> 5;
    const int lane = threadIdx.x & 31;
    const int row  = blockIdx.x * 8 + wid;
    const size_t base = (size_t)row * S;
    const float4* in4 = reinterpret_cast<const float4*>(x + base);

    float4 v[8];
    float s = 0.f, ss = 0.f;
    #pragma unroll
    for (int i = 0; i < 8; i++) {
        v[i] = in4[lane + 32 * i];
        s  += v[i].x + v[i].y + v[i].z + v[i].w;
        ss += v[i].x * v[i].x + v[i].y * v[i].y + v[i].z * v[i].z + v[i].w * v[i].w;
    }
    #pragma unroll
    for (int o = 16; o; o >>= 1) {
        s  += __shfl_xor_sync(0xFFFFFFFFu, s,  o);
        ss += __shfl_xor_sync(0xFFFFFFFFu, ss, o);
    }
    const float mean  = s * (1.0f / S);
    const float rss   = fmaxf(ss - s * mean, 0.0f);
    const float scale = 1.0f / (sqrtf(rss) + 1e-8f);

    uint2* out4 = reinterpret_cast<uint2*>(g_xn + base);
    #pragma unroll
    for (int i = 0; i < 8; i++) {
        __nv_bfloat162 h0 = __floats2bfloat162_rn((v[i].x - mean) * scale, (v[i].y - mean) * scale);
        __nv_bfloat162 h1 = __floats2bfloat162_rn((v[i].z - mean) * scale, (v[i].w - mean) * scale);
        uint2 p;
        p.x = *reinterpret_cast<uint32_t*>(&h0);
        p.y = *reinterpret_cast<uint32_t*>(&h1);
        out4[lane + 32 * i] = p;
    }
}

// ---------------------------------------------------------------------------
// Kernel 2: Gram tile, mma.sync bf16, 3-stage cp.async pipeline,
// register-double-buffered fragments, single sync per chunk.
// ---------------------------------------------------------------------------
__global__ __launch_bounds__(TPB, 2) void gram_abs_kernel() {
    extern __shared__ __align__(128) char dsmem[];
    __shared__ float s_red[8];

    const int tid  = threadIdx.x;
    const int wid  = tid >> 5;
    const int lane = tid & 31;
    const int warp_m = wid & 1;
    const int warp_n = wid >> 1;

    const int bx = blockIdx.x;
    const int batch = bx / TILES_PER_BATCH;
    int t = bx % TILES_PER_BATCH;
    int ti = 0;
    while (t >= 8 - ti) { t -= 8 - ti; ti++; }
    const int tj = ti + t;
    const bool diag = (ti == tj);

    const __nv_bfloat16* gA = g_xn + ((size_t)batch * C + ti * BM) * S;
    const __nv_bfloat16* gB = g_xn + ((size_t)batch * C + tj * BN) * S;

    const uint32_t smem_base = (uint32_t)__cvta_generic_to_shared(dsmem);

    // loader: A always; B skipped for diagonal tiles (sB aliases sA)
    auto load_chunk = [&](int cch, int stage) {
        const int k0 = cch * BK;
        const uint32_t sA = smem_base + stage * STAGE_BYTES;
        const uint32_t sB = sA + TILE_BYTES;
        #pragma unroll
        for (int it = 0; it < 4; it++) {
            int idx = it * TPB + tid;
            int r   = idx >> 3;
            int c16 = idx & 7;
            uint32_t dst = swz(r, c16 * 8);
            const size_t goff = (size_t)r * S + k0 + c16 * 8;
            cp_async16(sA + dst, gA + goff);
            if (!diag) cp_async16(sB + dst, gB + goff);
        }
    };

    const int a_row = warp_m * 64 + (lane & 15);
    const int a_col = (lane >> 4) * 8;
    const int b_row = warp_n * 32 + (lane & 7) + ((lane >> 4) << 3);
    const int b_col = ((lane >> 3) & 1) * 8;

    float acc[4][4][4];
    #pragma unroll
    for (int i = 0; i < 4; i++)
        #pragma unroll
        for (int j = 0; j < 4; j++)
            #pragma unroll
            for (int r = 0; r < 4; r++) acc[i][j][r] = 0.0f;

    load_chunk(0, 0); CP_COMMIT();
    load_chunk(1, 1); CP_COMMIT();

    uint32_t a[2][4][4];   // double-buffered A frags [buf][mf][reg]
    uint32_t b[2][4][2];   // double-buffered B frags [buf][nf][reg]

    auto load_frags = [&](int buf, uint32_t sA, uint32_t sB, int kk) {
        #pragma unroll
        for (int mf = 0; mf < 4; mf++) {
            uint32_t addr = sA + swz(a_row + mf * 16, a_col + kk);
            ldm_x4(a[buf][mf][0], a[buf][mf][1], a[buf][mf][2], a[buf][mf][3], addr);
        }
        uint32_t addr0 = sB + swz(b_row, b_col + kk);
        ldm_x4(b[buf][0][0], b[buf][0][1], b[buf][1][0], b[buf][1][1], addr0);
        uint32_t addr1 = sB + swz(b_row + 16, b_col + kk);
        ldm_x4(b[buf][2][0], b[buf][2][1], b[buf][3][0], b[buf][3][1], addr1);
    };

    for (int cch = 0; cch < NCHUNK; cch++) {
        const int stage = cch % STAGES;
        CP_WAIT(1);
        __syncthreads();   // chunk cch visible; compute(cch-1) finished by all warps

        // refill the stage freed by compute(cch-1)
        if (cch + 2 < NCHUNK) {
            load_chunk(cch + 2, (cch + 2) % STAGES);
            CP_COMMIT();
        }

        const uint32_t sA = smem_base + stage * STAGE_BYTES;
        const uint32_t sB = diag ? sA : (sA + TILE_BYTES);

        load_frags(0, sA, sB, 0);
        #pragma unroll
        for (int ks = 0; ks < BK / 16; ks++) {
            const int cur = ks & 1;
            if (ks + 1 < BK / 16) load_frags(cur ^ 1, sA, sB, (ks + 1) * 16);
            #pragma unroll
            for (int mf = 0; mf < 4; mf++)
                #pragma unroll
                for (int nf = 0; nf < 4; nf++)
                    mma16816(acc[mf][nf], a[cur][mf], b[cur][nf]);
        }
        // NOTE: no trailing sync — the top-of-loop sync of iter cch+1 orders
        // all warps' compute(cch) before load_chunk(cch+3) overwrites this stage.
    }

    // Epilogue: sum |corr| over strictly-upper entries
    const int groupID = lane >> 2;
    const int tid4    = lane & 3;
    float lsum = 0.0f;
    #pragma unroll
    for (int mf = 0; mf < 4; mf++) {
        #pragma unroll
        for (int nf = 0; nf < 4; nf++) {
            int gi = ti * BM + warp_m * 64 + mf * 16 + groupID;
            int gj = tj * BN + warp_n * 32 + nf * 8 + tid4 * 2;
            if (gj     > gi)     lsum += fabsf(acc[mf][nf][0]);
            if (gj + 1 > gi)     lsum += fabsf(acc[mf][nf][1]);
            if (gj     > gi + 8) lsum += fabsf(acc[mf][nf][2]);
            if (gj + 1 > gi + 8) lsum += fabsf(acc[mf][nf][3]);
        }
    }
    #pragma unroll
    for (int o = 16; o; o >>= 1) lsum += __shfl_xor_sync(0xFFFFFFFFu, lsum, o);

    if (lane == 0) s_red[wid] = lsum;
    __syncthreads();
    if (tid == 0) {
        float bsum = 0.f;
        #pragma unroll
        for (int w = 0; w < 8; w++) bsum += s_red[w];
        g_partials[bx] = bsum;
    }
}

// ---------------------------------------------------------------------------
__global__ __launch_bounds__(256) void finalize_kernel(float* __restrict__ out) {
    float s = 0.0f;
    for (int i = threadIdx.x; i < NBLK2; i += 256) s += g_partials[i];
    #pragma unroll
    for (int o = 16; o; o >>= 1) s += __shfl_xor_sync(0xFFFFFFFFu, s, o);

    __shared__ float red[8];
    const int wid = threadIdx.x >> 5;
    if ((threadIdx.x & 31) == 0) red[wid] = s;
    __syncthreads();
    if (threadIdx.x == 0) {
        float tot = 0.f;
        #pragma unroll
        for (int w = 0; w < 8; w++) tot += red[w];
        const float comb = (float)C * (C - 1) * 0.5f;
        out[0] = tot / (comb * (float)NB);
    }
}

// ---------------------------------------------------------------------------
extern "C" void kernel_launch(void* const* d_in, const int* in_sizes, int n_in,
                              void* d_out, int out_size) {
    const float* x = (const float*)d_in[0];
    float* out = (float*)d_out;

    cudaFuncSetAttribute(gram_abs_kernel,
                         cudaFuncAttributeMaxDynamicSharedMemorySize, DSMEM_BYTES);

    normalize_kernel<<<NB * C / 8, 256>>>(x);
    gram_abs_kernel<<<NBLK2, TPB, DSMEM_BYTES>>>();
    finalize_kernel<<<1, 256>>>(out);
}

// round 6
// speedup vs baseline: 1.0310x; 1.0310x over previous
#include <cuda_runtime.h>
#include <cuda_bf16.h>
#include <cstdint>

// ---------------------------------------------------------------------------
#define NB   32
#define C    1024
#define S    1024
#define BM   128
#define BN   128
#define BK   64                       // 64 bf16 = 128 B per tile row
#define NCHUNK (S / BK)               // 16
#define TILES_PER_BATCH 36
#define NBLK2 (NB * TILES_PER_BATCH)  // 1152
#define TPB  128                      // 4 warps, each 64x64
#define STAGES 3
#define TILE_BYTES (BM * 128)         // 16384
#define STAGE_BYTES (2 * TILE_BYTES)
#define DSMEM_BYTES (STAGES * STAGE_BYTES)   // 98304

__device__ __nv_bfloat16 g_xn[(size_t)NB * C * S];
__device__ float g_partials[NBLK2];

// ---------------------------------------------------------------------------
__device__ __forceinline__ void cp_async16(uint32_t smem_addr, const void* gptr) {
    asm volatile("cp.async.cg.shared.global [%0], [%1], 16;" :: "r"(smem_addr), "l"(gptr));
}
#define CP_COMMIT() asm volatile("cp.async.commit_group;" ::: "memory")
#define CP_WAIT(n)  asm volatile("cp.async.wait_group %0;" :: "n"(n) : "memory")

__device__ __forceinline__ void ldm_x4(uint32_t& r0, uint32_t& r1, uint32_t& r2, uint32_t& r3,
                                       uint32_t addr) {
    asm volatile("ldmatrix.sync.aligned.m8n8.x4.shared.b16 {%0,%1,%2,%3}, [%4];\n"
                 : "=r"(r0), "=r"(r1), "=r"(r2), "=r"(r3) : "r"(addr));
}

__device__ __forceinline__ void mma16816(float* d, const uint32_t* a, const uint32_t* b) {
    asm volatile("mma.sync.aligned.m16n8k16.row.col.f32.bf16.bf16.f32 "
                 "{%0,%1,%2,%3}, {%4,%5,%6,%7}, {%8,%9}, {%0,%1,%2,%3};\n"
                 : "+f"(d[0]), "+f"(d[1]), "+f"(d[2]), "+f"(d[3])
                 : "r"(a[0]), "r"(a[1]), "r"(a[2]), "r"(a[3]), "r"(b[0]), "r"(b[1]));
}

// XOR swizzle for 128B rows (SW128-equivalent)
__device__ __forceinline__ uint32_t swz(int row, int col_elems) {
    uint32_t chunk = (uint32_t)(col_elems >> 3);
    return (uint32_t)(row * 128) + (((chunk ^ ((uint32_t)row & 7u)) << 4));
}

// ---------------------------------------------------------------------------
// Kernel 1: normalize — one warp per row (at DRAM roofline; unchanged)
// ---------------------------------------------------------------------------
__global__ __launch_bounds__(256) void normalize_kernel(const float* __restrict__ x) {
    const int wid  = threadIdx.x >> 5;
    const int lane = threadIdx.x & 31;
    const int row  = blockIdx.x * 8 + wid;
    const size_t base = (size_t)row * S;
    const float4* in4 = reinterpret_cast<const float4*>(x + base);

    float4 v[8];
    float s = 0.f, ss = 0.f;
    #pragma unroll
    for (int i = 0; i < 8; i++) {
        v[i] = in4[lane + 32 * i];
        s  += v[i].x + v[i].y + v[i].z + v[i].w;
        ss += v[i].x * v[i].x + v[i].y * v[i].y + v[i].z * v[i].z + v[i].w * v[i].w;
    }
    #pragma unroll
    for (int o = 16; o; o >>= 1) {
        s  += __shfl_xor_sync(0xFFFFFFFFu, s,  o);
        ss += __shfl_xor_sync(0xFFFFFFFFu, ss, o);
    }
    const float mean  = s * (1.0f / S);
    const float rss   = fmaxf(ss - s * mean, 0.0f);
    const float scale = 1.0f / (sqrtf(rss) + 1e-8f);

    uint2* out4 = reinterpret_cast<uint2*>(g_xn + base);
    #pragma unroll
    for (int i = 0; i < 8; i++) {
        __nv_bfloat162 h0 = __floats2bfloat162_rn((v[i].x - mean) * scale, (v[i].y - mean) * scale);
        __nv_bfloat162 h1 = __floats2bfloat162_rn((v[i].z - mean) * scale, (v[i].w - mean) * scale);
        uint2 p;
        p.x = *reinterpret_cast<uint32_t*>(&h0);
        p.y = *reinterpret_cast<uint32_t*>(&h1);
        out4[lane + 32 * i] = p;
    }
}

// ---------------------------------------------------------------------------
// Kernel 2: Gram tile. 4 warps, each a 64x64 sub-tile (halves smem read
// amplification vs 64x32 warps). Single-buffered frags (ptxas pipelines),
// 3-stage cp.async, one sync per chunk, diagonal B-elision.
// ---------------------------------------------------------------------------
__global__ __launch_bounds__(TPB, 2) void gram_abs_kernel() {
    extern __shared__ __align__(128) char dsmem[];
    __shared__ float s_red[4];

    const int tid  = threadIdx.x;
    const int wid  = tid >> 5;
    const int lane = tid & 31;
    const int warp_m = wid & 1;            // 2 x 64 rows
    const int warp_n = wid >> 1;           // 2 x 64 cols

    const int bx = blockIdx.x;
    const int batch = bx / TILES_PER_BATCH;
    int t = bx % TILES_PER_BATCH;
    int ti = 0;
    while (t >= 8 - ti) { t -= 8 - ti; ti++; }
    const int tj = ti + t;
    const bool diag = (ti == tj);

    const __nv_bfloat16* gA = g_xn + ((size_t)batch * C + ti * BM) * S;
    const __nv_bfloat16* gB = g_xn + ((size_t)batch * C + tj * BN) * S;

    const uint32_t smem_base = (uint32_t)__cvta_generic_to_shared(dsmem);

    // loader: 128 threads; A always, B elided on diagonal tiles
    auto load_chunk = [&](int cch, int stage) {
        const int k0 = cch * BK;
        const uint32_t sA = smem_base + stage * STAGE_BYTES;
        const uint32_t sB = sA + TILE_BYTES;
        #pragma unroll
        for (int it = 0; it < 8; it++) {
            int idx = it * TPB + tid;          // 0..1023
            int r   = idx >> 3;
            int c16 = idx & 7;
            uint32_t dst = swz(r, c16 * 8);
            const size_t goff = (size_t)r * S + k0 + c16 * 8;
            cp_async16(sA + dst, gA + goff);
            if (!diag) cp_async16(sB + dst, gB + goff);
        }
    };

    // ldmatrix lane geometry
    const int a_row = warp_m * 64 + (lane & 15);
    const int a_col = (lane >> 4) * 8;
    const int b_row = warp_n * 64 + (lane & 7) + ((lane >> 4) << 3);
    const int b_col = ((lane >> 3) & 1) * 8;

    float acc[4][8][4];
    #pragma unroll
    for (int i = 0; i < 4; i++)
        #pragma unroll
        for (int j = 0; j < 8; j++)
            #pragma unroll
            for (int r = 0; r < 4; r++) acc[i][j][r] = 0.0f;

    load_chunk(0, 0); CP_COMMIT();
    load_chunk(1, 1); CP_COMMIT();

    for (int cch = 0; cch < NCHUNK; cch++) {
        const int stage = cch % STAGES;
        CP_WAIT(1);
        __syncthreads();   // chunk cch resident; compute(cch-1) done by all warps

        if (cch + 2 < NCHUNK) {
            load_chunk(cch + 2, (cch + 2) % STAGES);
            CP_COMMIT();
        }

        const uint32_t sA = smem_base + stage * STAGE_BYTES;
        const uint32_t sB = diag ? sA : (sA + TILE_BYTES);

        #pragma unroll
        for (int kk = 0; kk < BK; kk += 16) {
            uint32_t a[4][4];
            #pragma unroll
            for (int mf = 0; mf < 4; mf++) {
                uint32_t addr = sA + swz(a_row + mf * 16, a_col + kk);
                ldm_x4(a[mf][0], a[mf][1], a[mf][2], a[mf][3], addr);
            }
            uint32_t b[8][2];
            #pragma unroll
            for (int bb = 0; bb < 4; bb++) {
                uint32_t addr = sB + swz(b_row + bb * 16, b_col + kk);
                ldm_x4(b[bb * 2][0], b[bb * 2][1], b[bb * 2 + 1][0], b[bb * 2 + 1][1], addr);
            }
            #pragma unroll
            for (int mf = 0; mf < 4; mf++)
                #pragma unroll
                for (int nf = 0; nf < 8; nf++)
                    mma16816(acc[mf][nf], a[mf], b[nf]);
        }
        // no trailing sync: top-of-loop sync of iter cch+1 protects stage reuse
    }

    // Epilogue: sum |corr| over strictly-upper entries
    const int groupID = lane >> 2;
    const int tid4    = lane & 3;
    float lsum = 0.0f;
    #pragma unroll
    for (int mf = 0; mf < 4; mf++) {
        #pragma unroll
        for (int nf = 0; nf < 8; nf++) {
            int gi = ti * BM + warp_m * 64 + mf * 16 + groupID;
            int gj = tj * BN + warp_n * 64 + nf * 8 + tid4 * 2;
            if (gj     > gi)     lsum += fabsf(acc[mf][nf][0]);
            if (gj + 1 > gi)     lsum += fabsf(acc[mf][nf][1]);
            if (gj     > gi + 8) lsum += fabsf(acc[mf][nf][2]);
            if (gj + 1 > gi + 8) lsum += fabsf(acc[mf][nf][3]);
        }
    }
    #pragma unroll
    for (int o = 16; o; o >>= 1) lsum += __shfl_xor_sync(0xFFFFFFFFu, lsum, o);

    if (lane == 0) s_red[wid] = lsum;
    __syncthreads();
    if (tid == 0) {
        g_partials[bx] = s_red[0] + s_red[1] + s_red[2] + s_red[3];
    }
}

// ---------------------------------------------------------------------------
__global__ __launch_bounds__(256) void finalize_kernel(float* __restrict__ out) {
    float s = 0.0f;
    for (int i = threadIdx.x; i < NBLK2; i += 256) s += g_partials[i];
    #pragma unroll
    for (int o = 16; o; o >>= 1) s += __shfl_xor_sync(0xFFFFFFFFu, s, o);

    __shared__ float red[8];
    const int wid = threadIdx.x >> 5;
    if ((threadIdx.x & 31) == 0) red[wid] = s;
    __syncthreads();
    if (threadIdx.x == 0) {
        float tot = 0.f;
        #pragma unroll
        for (int w = 0; w < 8; w++) tot += red[w];
        const float comb = (float)C * (C - 1) * 0.5f;
        out[0] = tot / (comb * (float)NB);
    }
}

// ---------------------------------------------------------------------------
extern "C" void kernel_launch(void* const* d_in, const int* in_sizes, int n_in,
                              void* d_out, int out_size) {
    const float* x = (const float*)d_in[0];
    float* out = (float*)d_out;

    cudaFuncSetAttribute(gram_abs_kernel,
                         cudaFuncAttributeMaxDynamicSharedMemorySize, DSMEM_BYTES);

    normalize_kernel<<<NB * C / 8, 256>>>(x);
    gram_abs_kernel<<<NBLK2, TPB, DSMEM_BYTES>>>();
    finalize_kernel<<<1, 256>>>(out);
}

// round 8
// speedup vs baseline: 1.5860x; 1.5383x over previous
#include <cuda_runtime.h>
#include <cuda_bf16.h>
#include <cstdint>

// ---------------------------------------------------------------------------
#define NB   32
#define C    1024
#define S    1024
#define BM   128
#define BN   128
#define BKB  128                      // K-chunk in BYTES (=128 int8 elems)
#define NCHUNK (S / BKB)              // 8
#define TILES_PER_BATCH 36
#define NBLK2 (NB * TILES_PER_BATCH)  // 1152
#define TPB  256
#define STAGES 3
#define TILE_BYTES (BM * BKB)         // 16384
#define STAGE_BYTES (2 * TILE_BYTES)
#define DSMEM_BYTES (STAGES * STAGE_BYTES)   // 98304

// Scratch: int8 normalized rows (32 MB) + per-row scales + partials
__device__ int8_t g_xq[(size_t)NB * C * S];
__device__ float  g_scale[NB * C];
__device__ float  g_partials[NBLK2];

// ---------------------------------------------------------------------------
__device__ __forceinline__ void cp_async16(uint32_t smem_addr, const void* gptr) {
    asm volatile("cp.async.cg.shared.global [%0], [%1], 16;" :: "r"(smem_addr), "l"(gptr));
}
#define CP_COMMIT() asm volatile("cp.async.commit_group;" ::: "memory")
#define CP_WAIT(n)  asm volatile("cp.async.wait_group %0;" :: "n"(n) : "memory")

__device__ __forceinline__ void ldm_x4(uint32_t& r0, uint32_t& r1, uint32_t& r2, uint32_t& r3,
                                       uint32_t addr) {
    asm volatile("ldmatrix.sync.aligned.m8n8.x4.shared.b16 {%0,%1,%2,%3}, [%4];\n"
                 : "=r"(r0), "=r"(r1), "=r"(r2), "=r"(r3) : "r"(addr));
}

// int8 MMA: m16n8k32, s32 accumulate (exact). s8-k32 fragment layout is
// byte-identical to bf16-k16, so ldmatrix.b16 feeds it unchanged.
__device__ __forceinline__ void mma16832_s8(int* d, const uint32_t* a, const uint32_t* b) {
    asm volatile("mma.sync.aligned.m16n8k32.row.col.s32.s8.s8.s32 "
                 "{%0,%1,%2,%3}, {%4,%5,%6,%7}, {%8,%9}, {%0,%1,%2,%3};\n"
                 : "+r"(d[0]), "+r"(d[1]), "+r"(d[2]), "+r"(d[3])
                 : "r"(a[0]), "r"(a[1]), "r"(a[2]), "r"(a[3]), "r"(b[0]), "r"(b[1]));
}

// XOR swizzle for 128B rows; byteoff must be a multiple of 16
__device__ __forceinline__ uint32_t swzB(int row, int byteoff) {
    uint32_t chunk = (uint32_t)(byteoff >> 4);
    return (uint32_t)(row * 128) + ((chunk ^ ((uint32_t)row & 7u)) << 4);
}

// ---------------------------------------------------------------------------
// Kernel 1: normalize + int8 quantize — one warp per row.
// q = rint(xc * 127/max|xc|);  scale_row = max|xc| * inv_nrm / 127
// (so y_c . y_d = scale_c*scale_d * sum(q_c*q_d) exactly up to rounding)
// ---------------------------------------------------------------------------
__global__ __launch_bounds__(256) void normalize_kernel(const float* __restrict__ x) {
    const int wid  = threadIdx.x >> 5;
    const int lane = threadIdx.x & 31;
    const int row  = blockIdx.x * 8 + wid;
    const size_t base = (size_t)row * S;
    const float4* in4 = reinterpret_cast<const float4*>(x + base);

    float4 v[8];
    float s = 0.f, ss = 0.f;
    #pragma unroll
    for (int i = 0; i < 8; i++) {
        v[i] = in4[lane + 32 * i];
        s  += v[i].x + v[i].y + v[i].z + v[i].w;
        ss += v[i].x * v[i].x + v[i].y * v[i].y + v[i].z * v[i].z + v[i].w * v[i].w;
    }
    #pragma unroll
    for (int o = 16; o; o >>= 1) {
        s  += __shfl_xor_sync(0xFFFFFFFFu, s,  o);
        ss += __shfl_xor_sync(0xFFFFFFFFu, ss, o);
    }
    const float mean = s * (1.0f / S);

    float mx = 0.f;
    #pragma unroll
    for (int i = 0; i < 8; i++) {
        mx = fmaxf(mx, fabsf(v[i].x - mean));
        mx = fmaxf(mx, fabsf(v[i].y - mean));
        mx = fmaxf(mx, fabsf(v[i].z - mean));
        mx = fmaxf(mx, fabsf(v[i].w - mean));
    }
    #pragma unroll
    for (int o = 16; o; o >>= 1)
        mx = fmaxf(mx, __shfl_xor_sync(0xFFFFFFFFu, mx, o));
    mx = fmaxf(mx, 1e-20f);

    const float rss = fmaxf(ss - s * mean, 0.0f);
    const float inv_nrm = 1.0f / (sqrtf(rss) + 1e-8f);
    const float qmul = 127.0f / mx;

    if (lane == 0) g_scale[row] = mx * inv_nrm * (1.0f / 127.0f);

    // thread handles elements {lane*4 + 128*i .. +3} (matching the float4 reads)
    uint32_t* out = reinterpret_cast<uint32_t*>(g_xq + base);
    #pragma unroll
    for (int i = 0; i < 8; i++) {
        int a0 = __float2int_rn((v[i].x - mean) * qmul);
        int a1 = __float2int_rn((v[i].y - mean) * qmul);
        int a2 = __float2int_rn((v[i].z - mean) * qmul);
        int a3 = __float2int_rn((v[i].w - mean) * qmul);
        uint32_t w = (a0 & 0xFF) | ((a1 & 0xFF) << 8) | ((a2 & 0xFF) << 16)
                   | (((uint32_t)a3 & 0xFF) << 24);
        out[lane + 32 * i] = w;
    }
}

// ---------------------------------------------------------------------------
// Kernel 2: int8 Gram tile (8 warps of 64x32), 3-stage cp.async, single sync
// per chunk, diagonal B-elision, per-row-scale epilogue + masked |.| sum.
// ---------------------------------------------------------------------------
__global__ __launch_bounds__(TPB, 2) void gram_abs_kernel() {
    extern __shared__ __align__(128) char dsmem[];
    __shared__ float sScA[BM];
    __shared__ float sScB[BN];
    __shared__ float s_red[8];

    const int tid  = threadIdx.x;
    const int wid  = tid >> 5;
    const int lane = tid & 31;
    const int warp_m = wid & 1;            // 2 x 64 rows
    const int warp_n = wid >> 1;           // 4 x 32 cols

    const int bx = blockIdx.x;
    const int batch = bx / TILES_PER_BATCH;
    int t = bx % TILES_PER_BATCH;
    int ti = 0;
    while (t >= 8 - ti) { t -= 8 - ti; ti++; }
    const int tj = ti + t;
    const bool diag = (ti == tj);

    const int8_t* gA = g_xq + ((size_t)batch * C + ti * BM) * S;
    const int8_t* gB = g_xq + ((size_t)batch * C + tj * BN) * S;

    // stage row scales (256 threads: 128 A + 128 B)
    if (tid < BM) sScA[tid] = g_scale[batch * C + ti * BM + tid];
    else          sScB[tid - BM] = g_scale[batch * C + tj * BN + (tid - BM)];

    const uint32_t smem_base = (uint32_t)__cvta_generic_to_shared(dsmem);

    auto load_chunk = [&](int cch, int stage) {
        const int k0 = cch * BKB;
        const uint32_t sA = smem_base + stage * STAGE_BYTES;
        const uint32_t sB = sA + TILE_BYTES;
        #pragma unroll
        for (int it = 0; it < 4; it++) {
            int idx = it * TPB + tid;          // 0..1023
            int r   = idx >> 3;
            int c16 = idx & 7;                 // 16B chunk within 128B row
            uint32_t dst = swzB(r, c16 * 16);
            const size_t goff = (size_t)r * S + k0 + c16 * 16;
            cp_async16(sA + dst, gA + goff);
            if (!diag) cp_async16(sB + dst, gB + goff);
        }
    };

    // ldmatrix lane geometry (byte columns)
    const int a_row  = warp_m * 64 + (lane & 15);
    const int a_colB = (lane >> 4) * 16;
    const int b_row  = warp_n * 32 + (lane & 7) + ((lane >> 4) << 3);
    const int b_colB = ((lane >> 3) & 1) * 16;

    int acc[4][4][4];
    #pragma unroll
    for (int i = 0; i < 4; i++)
        #pragma unroll
        for (int j = 0; j < 4; j++)
            #pragma unroll
            for (int r = 0; r < 4; r++) acc[i][j][r] = 0;

    load_chunk(0, 0); CP_COMMIT();
    load_chunk(1, 1); CP_COMMIT();

    for (int cch = 0; cch < NCHUNK; cch++) {
        const int stage = cch % STAGES;
        CP_WAIT(1);
        __syncthreads();   // chunk cch resident; compute(cch-1) done by all warps

        if (cch + 2 < NCHUNK) {
            load_chunk(cch + 2, (cch + 2) % STAGES);
            CP_COMMIT();
        }

        const uint32_t sA = smem_base + stage * STAGE_BYTES;
        const uint32_t sB = diag ? sA : (sA + TILE_BYTES);

        #pragma unroll
        for (int kk = 0; kk < 4; kk++) {           // 4 x k32 per 128B chunk
            const int kb = kk * 32;
            uint32_t a[4][4];
            #pragma unroll
            for (int mf = 0; mf < 4; mf++) {
                uint32_t addr = sA + swzB(a_row + mf * 16, kb + a_colB);
                ldm_x4(a[mf][0], a[mf][1], a[mf][2], a[mf][3], addr);
            }
            uint32_t b[4][2];
            {
                uint32_t addr0 = sB + swzB(b_row, kb + b_colB);
                ldm_x4(b[0][0], b[0][1], b[1][0], b[1][1], addr0);
                uint32_t addr1 = sB + swzB(b_row + 16, kb + b_colB);
                ldm_x4(b[2][0], b[2][1], b[3][0], b[3][1], addr1);
            }
            #pragma unroll
            for (int mf = 0; mf < 4; mf++)
                #pragma unroll
                for (int nf = 0; nf < 4; nf++)
                    mma16832_s8(acc[mf][nf], a[mf], b[nf]);
        }
        // no trailing sync: top-of-loop sync of iter cch+1 protects stage reuse
    }

    // Epilogue: rescale each entry by sA[i]*sB[j], mask strictly-upper, abs-sum
    const int groupID = lane >> 2;
    const int tid4    = lane & 3;
    float lsum = 0.0f;
    #pragma unroll
    for (int mf = 0; mf < 4; mf++) {
        const int li0 = warp_m * 64 + mf * 16 + groupID;   // local row of regs 0,1
        const int li1 = li0 + 8;                           // local row of regs 2,3
        const float sa0 = sScA[li0];
        const float sa1 = sScA[li1];
        const int gi0 = ti * BM + li0;
        const int gi1 = ti * BM + li1;
        #pragma unroll
        for (int nf = 0; nf < 4; nf++) {
            const int lj = warp_n * 32 + nf * 8 + tid4 * 2;
            const int gj = tj * BN + lj;
            const float sb0 = sScB[lj];
            const float sb1 = sScB[lj + 1];
            if (gj     > gi0) lsum += fabsf((float)acc[mf][nf][0] * sa0 * sb0);
            if (gj + 1 > gi0) lsum += fabsf((float)acc[mf][nf][1] * sa0 * sb1);
            if (gj     > gi1) lsum += fabsf((float)acc[mf][nf][2] * sa1 * sb0);
            if (gj + 1 > gi1) lsum += fabsf((float)acc[mf][nf][3] * sa1 * sb1);
        }
    }
    #pragma unroll
    for (int o = 16; o; o >>= 1) lsum += __shfl_xor_sync(0xFFFFFFFFu, lsum, o);

    if (lane == 0) s_red[wid] = lsum;
    __syncthreads();
    if (tid == 0) {
        float bsum = 0.f;
        #pragma unroll
        for (int w = 0; w < 8; w++) bsum += s_red[w];
        g_partials[bx] = bsum;
    }
}

// ---------------------------------------------------------------------------
// Kernel 3: deterministic final reduction + scaling.
// avg = U / (comb * N), comb = C*(C-1)/2 (total offdiag = 2U)
// ---------------------------------------------------------------------------
__global__ __launch_bounds__(256) void finalize_kernel(float* __restrict__ out) {
    float s = 0.0f;
    for (int i = threadIdx.x; i < NBLK2; i += 256) s += g_partials[i];
    #pragma unroll
    for (int o = 16; o; o >>= 1) s += __shfl_xor_sync(0xFFFFFFFFu, s, o);

    __shared__ float red[8];
    const int wid = threadIdx.x >> 5;
    if ((threadIdx.x & 31) == 0) red[wid] = s;
    __syncthreads();
    if (threadIdx.x == 0) {
        float tot = 0.f;
        #pragma unroll
        for (int w = 0; w < 8; w++) tot += red[w];
        const float comb = (float)C * (C - 1) * 0.5f;
        out[0] = tot / (comb * (float)NB);
    }
}

// ---------------------------------------------------------------------------
extern "C" void kernel_launch(void* const* d_in, const int* in_sizes, int n_in,
                              void* d_out, int out_size) {
    const float* x = (const float*)d_in[0];
    float* out = (float*)d_out;

    cudaFuncSetAttribute(gram_abs_kernel,
                         cudaFuncAttributeMaxDynamicSharedMemorySize, DSMEM_BYTES);

    normalize_kernel<<<NB * C / 8, 256>>>(x);
    gram_abs_kernel<<<NBLK2, TPB, DSMEM_BYTES>>>();
    finalize_kernel<<<1, 256>>>(out);
}